// round 3
// baseline (speedup 1.0000x reference)
#include <cuda_runtime.h>
#include <cstdint>

// QuantumDotProductCircuit:
//   ov(b) = a(b)^T M b(b),  score = |ov|^2, out = (1+score)/2
// a,b are real Kronecker product states from RY(tanh(x)*pi) on |0>,
// M = U_q^dagger U_k is a fixed 16x16 complex matrix built from W_q,W_k.

__device__ ulonglong2 g_M[128];  // 16x16 complex, interleaved (re,im), row-major

__device__ __forceinline__ unsigned long long pk2(float lo, float hi) {
    unsigned long long r;
    asm("mov.b64 %0, {%1, %2};" : "=l"(r) : "f"(lo), "f"(hi));
    return r;
}
__device__ __forceinline__ float2 upk2(unsigned long long v) {
    float2 r;
    asm("mov.b64 {%0, %1}, %2;" : "=f"(r.x), "=f"(r.y) : "l"(v));
    return r;
}
__device__ __forceinline__ unsigned long long fma2(unsigned long long a,
                                                   unsigned long long b,
                                                   unsigned long long c) {
    unsigned long long d;
    asm("fma.rn.f32x2 %0, %1, %2, %3;" : "=l"(d) : "l"(a), "l"(b), "l"(c));
    return d;
}
__device__ __forceinline__ unsigned long long add2(unsigned long long a,
                                                   unsigned long long b) {
    unsigned long long d;
    asm("add.rn.f32x2 %0, %1, %2;" : "=l"(d) : "l"(a), "l"(b));
    return d;
}

// fast tanh: (e^{2x}-1)/(e^{2x}+1), EX2 + RCP.approx. rel err ~1e-6.
__device__ __forceinline__ float fast_tanh(float x) {
    x = fminf(fmaxf(x, -9.0f), 9.0f);
    float e = __expf(2.0f * x);
    return __fdividef(e - 1.0f, e + 1.0f);
}

// ---------------------------------------------------------------------------
// Prep kernel: build U_q, U_k (16x16) by simulating the Rot+CNOT layers on
// each basis state, then M = U_q^dagger U_k. One block, 256 threads.
// Wire w maps to index bit (3-w) (reference reshape puts wire 0 as MSB).
// ---------------------------------------------------------------------------
__global__ void qdp_prep(const float* __restrict__ Wq, const float* __restrict__ Wk) {
    __shared__ float2 U[2][16][16];  // [matrix][row t][column c]
    int tid = threadIdx.x;

    if (tid < 32) {
        int m = tid >> 4;       // 0 = q, 1 = k
        int c = tid & 15;       // column = input basis state
        const float* W = m ? Wk : Wq;

        float vr[16], vi[16];
#pragma unroll
        for (int s = 0; s < 16; s++) { vr[s] = (s == c) ? 1.0f : 0.0f; vi[s] = 0.0f; }

#pragma unroll
        for (int layer = 0; layer < 2; layer++) {
#pragma unroll
            for (int w = 0; w < 4; w++) {
                float phi = W[layer * 12 + w * 3 + 0];
                float th  = W[layer * 12 + w * 3 + 1];
                float om  = W[layer * 12 + w * 3 + 2];
                float cth, sth; __sincosf(0.5f * th, &sth, &cth);
                float sA, cA, sB, cB;
                __sincosf(0.5f * (phi + om), &sA, &cA);
                __sincosf(0.5f * (phi - om), &sB, &cB);
                float u00r =  cA * cth, u00i = -sA * cth;
                float u01r = -cB * sth, u01i = -sB * sth;
                float u10r =  cB * sth, u10i = -sB * sth;
                float u11r =  cA * cth, u11i =  sA * cth;
                const int st = 8 >> w;
#pragma unroll
                for (int s = 0; s < 16; s++) {
                    if (!(s & st)) {
                        const int s1 = s | st;
                        float xr = vr[s], xi = vi[s], yr = vr[s1], yi = vi[s1];
                        vr[s]  = u00r * xr - u00i * xi + u01r * yr - u01i * yi;
                        vi[s]  = u00r * xi + u00i * xr + u01r * yi + u01i * yr;
                        vr[s1] = u10r * xr - u10i * xi + u11r * yr - u11i * yi;
                        vi[s1] = u10r * xi + u10i * xr + u11r * yi + u11i * yr;
                    }
                }
            }
#pragma unroll
            for (int w = 0; w < 3; w++) {
                const int cm = 8 >> w, tm = 4 >> w;
#pragma unroll
                for (int s = 0; s < 16; s++) {
                    if ((s & cm) && !(s & tm)) {
                        const int s1 = s | tm;
                        float tr = vr[s], ti = vi[s];
                        vr[s] = vr[s1]; vi[s] = vi[s1];
                        vr[s1] = tr;    vi[s1] = ti;
                    }
                }
            }
        }
#pragma unroll
        for (int t = 0; t < 16; t++) U[m][t][c] = make_float2(vr[t], vi[t]);
    }
    __syncthreads();

    // M[i][j] = sum_t conj(Uq[t][i]) * Uk[t][j]
    int i = tid >> 4, j = tid & 15;
    float mr = 0.0f, mi = 0.0f;
#pragma unroll
    for (int t = 0; t < 16; t++) {
        float2 q = U[0][t][i];
        float2 k = U[1][t][j];
        mr += q.x * k.x + q.y * k.y;
        mi += q.x * k.y - q.y * k.x;
    }
    float* gm = (float*)g_M;
    gm[2 * (i * 16 + j) + 0] = mr;
    gm[2 * (i * 16 + j) + 1] = mi;
}

// ---------------------------------------------------------------------------
// Per-element math: first 4 floats of q and k rows -> output score.
// ---------------------------------------------------------------------------
__device__ __forceinline__ float qdp_element(float4 qv, float4 kv,
                                             const ulonglong2* __restrict__ Msh) {
    const float HP = 1.5707963267948966f;  // pi/2 (half-angle scale)
    float cs[4], sn[4];
    __sincosf(fast_tanh(qv.x) * HP, &sn[0], &cs[0]);
    __sincosf(fast_tanh(qv.y) * HP, &sn[1], &cs[1]);
    __sincosf(fast_tanh(qv.z) * HP, &sn[2], &cs[2]);
    __sincosf(fast_tanh(qv.w) * HP, &sn[3], &cs[3]);
    float a01[4] = {cs[0]*cs[1], cs[0]*sn[1], sn[0]*cs[1], sn[0]*sn[1]};
    float a23[4] = {cs[2]*cs[3], cs[2]*sn[3], sn[2]*cs[3], sn[2]*sn[3]};

    __sincosf(fast_tanh(kv.x) * HP, &sn[0], &cs[0]);
    __sincosf(fast_tanh(kv.y) * HP, &sn[1], &cs[1]);
    __sincosf(fast_tanh(kv.z) * HP, &sn[2], &cs[2]);
    __sincosf(fast_tanh(kv.w) * HP, &sn[3], &cs[3]);
    float b01[4] = {cs[0]*cs[1], cs[0]*sn[1], sn[0]*cs[1], sn[0]*sn[1]};
    float b23[4] = {cs[2]*cs[3], cs[2]*sn[3], sn[2]*cs[3], sn[2]*sn[3]};

    unsigned long long bp[16];
#pragma unroll
    for (int j = 0; j < 16; j++) {
        float v = b01[j >> 2] * b23[j & 3];
        bp[j] = pk2(v, v);
    }

    // ov = sum_i av[i] * (sum_j M[i][j] * b[j]), packed (re,im) lanes.
    unsigned long long ov0 = 0ULL, ov1 = 0ULL;
#pragma unroll
    for (int i = 0; i < 16; i++) {
        unsigned long long t0 = 0ULL, t1 = 0ULL;
#pragma unroll
        for (int jj = 0; jj < 8; jj++) {
            ulonglong2 m = Msh[i * 8 + jj];     // two complex entries
            t0 = fma2(m.x, bp[2 * jj + 0], t0);
            t1 = fma2(m.y, bp[2 * jj + 1], t1);
        }
        float avi = a01[i >> 2] * a23[i & 3];
        unsigned long long avp = pk2(avi, avi);
        unsigned long long s = add2(t0, t1);
        if (i & 1) ov1 = fma2(avp, s, ov1);
        else       ov0 = fma2(avp, s, ov0);
    }
    float2 o = upk2(add2(ov0, ov1));
    float score = o.x * o.x + o.y * o.y;
    return fmaf(0.5f, score, 0.5f);
}

// ---------------------------------------------------------------------------
// Main kernel: 4 elements per thread, all 8 global loads front-batched so
// each warp keeps 8 LDG (256 distinct 128B lines) in flight while other
// warps compute. 128 threads/block, 512 elements/block.
// ---------------------------------------------------------------------------
__global__ void __launch_bounds__(128) qdp_main4(
        const float4* __restrict__ q4, const float4* __restrict__ k4,
        float* __restrict__ out, int B) {
    __shared__ ulonglong2 Msh[128];
    const int tid = threadIdx.x;
    const size_t e0 = (size_t)blockIdx.x * 512 + tid;   // elems e0 + {0,128,256,384}

    // Front-batched loads: rows are 64 floats = 16 float4, we need float4 #0.
    float4 q0 = __ldcs(&q4[(e0 +   0) * 16]);
    float4 q1 = __ldcs(&q4[(e0 + 128) * 16]);
    float4 q2 = __ldcs(&q4[(e0 + 256) * 16]);
    float4 q3 = __ldcs(&q4[(e0 + 384) * 16]);
    float4 k0 = __ldcs(&k4[(e0 +   0) * 16]);
    float4 k1 = __ldcs(&k4[(e0 + 128) * 16]);
    float4 k2 = __ldcs(&k4[(e0 + 256) * 16]);
    float4 k3 = __ldcs(&k4[(e0 + 384) * 16]);

    Msh[tid] = g_M[tid];
    __syncthreads();

    out[e0 +   0] = qdp_element(q0, k0, Msh);
    out[e0 + 128] = qdp_element(q1, k1, Msh);
    out[e0 + 256] = qdp_element(q2, k2, Msh);
    out[e0 + 384] = qdp_element(q3, k3, Msh);
}

// ---------------------------------------------------------------------------
// Tail kernel for non-multiple-of-512 sizes (not hit for B=262144).
// ---------------------------------------------------------------------------
__global__ void qdp_main_tail(const float4* __restrict__ q4, const float4* __restrict__ k4,
                              float* __restrict__ out, int start, int B) {
    __shared__ ulonglong2 Msh[128];
    int tid = threadIdx.x;
    if (tid < 128) Msh[tid] = g_M[tid];
    __syncthreads();
    int idx = start + blockIdx.x * 256 + tid;
    if (idx >= B) return;
    float4 qv = __ldcs(&q4[(size_t)idx * 16]);
    float4 kv = __ldcs(&k4[(size_t)idx * 16]);
    out[idx] = qdp_element(qv, kv, Msh);
}

extern "C" void kernel_launch(void* const* d_in, const int* in_sizes, int n_in,
                              void* d_out, int out_size) {
    const float* q  = (const float*)d_in[0];
    const float* k  = (const float*)d_in[1];
    const float* Wq = (const float*)d_in[2];
    const float* Wk = (const float*)d_in[3];
    int B = in_sizes[0] / 64;

    qdp_prep<<<1, 256>>>(Wq, Wk);

    int nfull = B / 512;            // blocks of 512 elements
    if (nfull > 0) {
        qdp_main4<<<nfull, 128>>>((const float4*)q, (const float4*)k,
                                  (float*)d_out, B);
    }
    int done = nfull * 512;
    if (done < B) {
        int rem = B - done;
        qdp_main_tail<<<(rem + 255) / 256, 256>>>((const float4*)q, (const float4*)k,
                                                  (float*)d_out, done, B);
    }
}

// round 5
// speedup vs baseline: 3.0377x; 3.0377x over previous
#include <cuda_runtime.h>
#include <cstdint>

// QuantumDotProductCircuit:
//   ov(b) = a(b)^T M b(b),  score = |ov|^2, out = (1+score)/2
// a,b are real Kronecker product states from RY(tanh(x)*pi) on |0>,
// M = U_q^dagger U_k is a fixed 16x16 complex matrix built from W_q,W_k.
// M stored as split real/imag planes of 256 floats each.

__device__ __align__(16) float g_Mr[256];  // M real, row-major 16x16
__device__ __align__(16) float g_Mi[256];  // M imag

__device__ __forceinline__ unsigned long long pk2(float lo, float hi) {
    unsigned long long r;
    asm("mov.b64 %0, {%1, %2};" : "=l"(r) : "f"(lo), "f"(hi));
    return r;
}
__device__ __forceinline__ float2 upk2(unsigned long long v) {
    float2 r;
    asm("mov.b64 {%0, %1}, %2;" : "=f"(r.x), "=f"(r.y) : "l"(v));
    return r;
}
__device__ __forceinline__ unsigned long long fma2(unsigned long long a,
                                                   unsigned long long b,
                                                   unsigned long long c) {
    unsigned long long d;
    asm("fma.rn.f32x2 %0, %1, %2, %3;" : "=l"(d) : "l"(a), "l"(b), "l"(c));
    return d;
}

// fast tanh: (e^{2x}-1)/(e^{2x}+1), EX2 + RCP.approx. rel err ~1e-6.
__device__ __forceinline__ float fast_tanh(float x) {
    x = fminf(fmaxf(x, -9.0f), 9.0f);
    float e = __expf(2.0f * x);
    return __fdividef(e - 1.0f, e + 1.0f);
}

// ---------------------------------------------------------------------------
// Prep kernel: build U_q, U_k (16x16) by simulating the Rot+CNOT layers on
// each basis state, then M = U_q^dagger U_k. One block, 256 threads.
// Wire w maps to index bit (3-w) (reference reshape puts wire 0 as MSB).
// ---------------------------------------------------------------------------
__global__ void qdp_prep(const float* __restrict__ Wq, const float* __restrict__ Wk) {
    __shared__ float2 U[2][16][16];  // [matrix][row t][column c]
    int tid = threadIdx.x;

    if (tid < 32) {
        int m = tid >> 4;       // 0 = q, 1 = k
        int c = tid & 15;       // column = input basis state
        const float* W = m ? Wk : Wq;

        float vr[16], vi[16];
#pragma unroll
        for (int s = 0; s < 16; s++) { vr[s] = (s == c) ? 1.0f : 0.0f; vi[s] = 0.0f; }

#pragma unroll
        for (int layer = 0; layer < 2; layer++) {
#pragma unroll
            for (int w = 0; w < 4; w++) {
                float phi = W[layer * 12 + w * 3 + 0];
                float th  = W[layer * 12 + w * 3 + 1];
                float om  = W[layer * 12 + w * 3 + 2];
                float cth, sth; __sincosf(0.5f * th, &sth, &cth);
                float sA, cA, sB, cB;
                __sincosf(0.5f * (phi + om), &sA, &cA);
                __sincosf(0.5f * (phi - om), &sB, &cB);
                float u00r =  cA * cth, u00i = -sA * cth;
                float u01r = -cB * sth, u01i = -sB * sth;
                float u10r =  cB * sth, u10i = -sB * sth;
                float u11r =  cA * cth, u11i =  sA * cth;
                const int st = 8 >> w;
#pragma unroll
                for (int s = 0; s < 16; s++) {
                    if (!(s & st)) {
                        const int s1 = s | st;
                        float xr = vr[s], xi = vi[s], yr = vr[s1], yi = vi[s1];
                        vr[s]  = u00r * xr - u00i * xi + u01r * yr - u01i * yi;
                        vi[s]  = u00r * xi + u00i * xr + u01r * yi + u01i * yr;
                        vr[s1] = u10r * xr - u10i * xi + u11r * yr - u11i * yi;
                        vi[s1] = u10r * xi + u10i * xr + u11r * yi + u11i * yr;
                    }
                }
            }
#pragma unroll
            for (int w = 0; w < 3; w++) {
                const int cm = 8 >> w, tm = 4 >> w;
#pragma unroll
                for (int s = 0; s < 16; s++) {
                    if ((s & cm) && !(s & tm)) {
                        const int s1 = s | tm;
                        float tr = vr[s], ti = vi[s];
                        vr[s] = vr[s1]; vi[s] = vi[s1];
                        vr[s1] = tr;    vi[s1] = ti;
                    }
                }
            }
        }
#pragma unroll
        for (int t = 0; t < 16; t++) U[m][t][c] = make_float2(vr[t], vi[t]);
    }
    __syncthreads();

    // M[i][j] = sum_t conj(Uq[t][i]) * Uk[t][j]
    int i = tid >> 4, j = tid & 15;
    float mr = 0.0f, mi = 0.0f;
#pragma unroll
    for (int t = 0; t < 16; t++) {
        float2 q = U[0][t][i];
        float2 k = U[1][t][j];
        mr += q.x * k.x + q.y * k.y;
        mi += q.x * k.y - q.y * k.x;
    }
    g_Mr[i * 16 + j] = mr;
    g_Mi[i * 16 + j] = mi;
}

// ---------------------------------------------------------------------------
// Main kernel: 1 element/thread, 128-thr blocks, register-lean (cap 42 via
// launch_bounds) so 12 blocks/SM are resident (75% occ, 1.15 waves).
// M in SMEM as split re/im planes; b packed as 8 (b2j,b2j+1) f32x2 pairs.
// ---------------------------------------------------------------------------
__global__ void __launch_bounds__(128, 12) qdp_main(
        const float4* __restrict__ q4, const float4* __restrict__ k4,
        float* __restrict__ out, int B) {
    // MshR[i*4+c].x = (Mr[i][4c],Mr[i][4c+1]), .y = (Mr[i][4c+2],Mr[i][4c+3])
    __shared__ ulonglong2 MshR[64];
    __shared__ ulonglong2 MshI[64];

    const int tid = threadIdx.x;
    const int idx0 = blockIdx.x * 128 + tid;
    const int idx = (idx0 < B) ? idx0 : (B - 1);   // clamped load index

    // rows are 64 floats = 16 float4; we need float4 #0 of each row
    float4 qv = __ldcs(&q4[(size_t)idx * 16]);
    float4 kv = __ldcs(&k4[(size_t)idx * 16]);

    // cooperative M load: 512 floats = 128 x 16B
    {
        const float4* gr = (const float4*)g_Mr;   // 64 float4
        const float4* gi = (const float4*)g_Mi;   // 64 float4
        if (tid < 64) ((float4*)MshR)[tid] = gr[tid];
        else          ((float4*)MshI)[tid - 64] = gi[tid - 64];
    }
    __syncthreads();

    const float HP = 1.5707963267948966f;  // pi/2
    float cs[4], sn[4];

    // a-side (query)
    __sincosf(fast_tanh(qv.x) * HP, &sn[0], &cs[0]);
    __sincosf(fast_tanh(qv.y) * HP, &sn[1], &cs[1]);
    __sincosf(fast_tanh(qv.z) * HP, &sn[2], &cs[2]);
    __sincosf(fast_tanh(qv.w) * HP, &sn[3], &cs[3]);
    float a01[4] = {cs[0]*cs[1], cs[0]*sn[1], sn[0]*cs[1], sn[0]*sn[1]};
    float a23[4] = {cs[2]*cs[3], cs[2]*sn[3], sn[2]*cs[3], sn[2]*sn[3]};

    // b-side (key) -> 8 packed pairs (b[2p], b[2p+1])
    __sincosf(fast_tanh(kv.x) * HP, &sn[0], &cs[0]);
    __sincosf(fast_tanh(kv.y) * HP, &sn[1], &cs[1]);
    __sincosf(fast_tanh(kv.z) * HP, &sn[2], &cs[2]);
    __sincosf(fast_tanh(kv.w) * HP, &sn[3], &cs[3]);
    float b01[4] = {cs[0]*cs[1], cs[0]*sn[1], sn[0]*cs[1], sn[0]*sn[1]};
    float b23[4] = {cs[2]*cs[3], cs[2]*sn[3], sn[2]*cs[3], sn[2]*sn[3]};

    unsigned long long bp[8];
#pragma unroll
    for (int p = 0; p < 8; p++) {
        int j0 = 2 * p, j1 = 2 * p + 1;
        bp[p] = pk2(b01[j0 >> 2] * b23[j0 & 3], b01[j1 >> 2] * b23[j1 & 3]);
    }

    // ov = sum_i avi * (row_i . b); re/im as 2-lane partial sums
    unsigned long long ov_re = 0ULL, ov_im = 0ULL;
#pragma unroll
    for (int i = 0; i < 16; i++) {
        unsigned long long t_re = 0ULL, t_im = 0ULL;
#pragma unroll
        for (int c = 0; c < 4; c++) {
            ulonglong2 mr = MshR[i * 4 + c];
            t_re = fma2(mr.x, bp[2 * c + 0], t_re);
            t_re = fma2(mr.y, bp[2 * c + 1], t_re);
            ulonglong2 mi = MshI[i * 4 + c];
            t_im = fma2(mi.x, bp[2 * c + 0], t_im);
            t_im = fma2(mi.y, bp[2 * c + 1], t_im);
        }
        float avi = a01[i >> 2] * a23[i & 3];
        unsigned long long avp = pk2(avi, avi);
        ov_re = fma2(avp, t_re, ov_re);
        ov_im = fma2(avp, t_im, ov_im);
    }

    float2 r2 = upk2(ov_re);
    float2 i2 = upk2(ov_im);
    float re = r2.x + r2.y;
    float im = i2.x + i2.y;
    float score = fmaf(re, re, im * im);
    if (idx0 < B) out[idx0] = fmaf(0.5f, score, 0.5f);
}

extern "C" void kernel_launch(void* const* d_in, const int* in_sizes, int n_in,
                              void* d_out, int out_size) {
    const float* q  = (const float*)d_in[0];
    const float* k  = (const float*)d_in[1];
    const float* Wq = (const float*)d_in[2];
    const float* Wk = (const float*)d_in[3];
    int B = in_sizes[0] / 64;

    qdp_prep<<<1, 256>>>(Wq, Wk);
    qdp_main<<<(B + 127) / 128, 128>>>((const float4*)q, (const float4*)k,
                                       (float*)d_out, B);
}

// round 6
// speedup vs baseline: 3.2304x; 1.0634x over previous
#include <cuda_runtime.h>
#include <cstdint>

// QuantumDotProductCircuit:
//   ov(b) = a(b)^T M b(b),  score = |ov|^2, out = (1+score)/2
// a,b are real Kronecker product states from RY(tanh(x)*pi) on |0>,
// M = U_q^dagger U_k is a fixed 16x16 complex matrix built from W_q,W_k.
// M stored as split real/imag planes of 256 floats each.

__device__ __align__(16) float g_Mr[256];  // M real, row-major 16x16
__device__ __align__(16) float g_Mi[256];  // M imag

__device__ __forceinline__ unsigned long long pk2(float lo, float hi) {
    unsigned long long r;
    asm("mov.b64 %0, {%1, %2};" : "=l"(r) : "f"(lo), "f"(hi));
    return r;
}
__device__ __forceinline__ float2 upk2(unsigned long long v) {
    float2 r;
    asm("mov.b64 {%0, %1}, %2;" : "=f"(r.x), "=f"(r.y) : "l"(v));
    return r;
}
__device__ __forceinline__ unsigned long long fma2(unsigned long long a,
                                                   unsigned long long b,
                                                   unsigned long long c) {
    unsigned long long d;
    asm("fma.rn.f32x2 %0, %1, %2, %3;" : "=l"(d) : "l"(a), "l"(b), "l"(c));
    return d;
}

// fast tanh: (e^{2x}-1)/(e^{2x}+1), EX2 + RCP.approx. rel err ~1e-6.
__device__ __forceinline__ float fast_tanh(float x) {
    x = fminf(fmaxf(x, -9.0f), 9.0f);
    float e = __expf(2.0f * x);
    return __fdividef(e - 1.0f, e + 1.0f);
}

// ---------------------------------------------------------------------------
// Prep kernel: build U_q, U_k (16x16) by simulating the Rot+CNOT layers on
// each basis state, then M = U_q^dagger U_k. One block, 256 threads.
// Wire w maps to index bit (3-w) (reference reshape puts wire 0 as MSB).
// ---------------------------------------------------------------------------
__global__ void qdp_prep(const float* __restrict__ Wq, const float* __restrict__ Wk) {
    __shared__ float2 U[2][16][16];  // [matrix][row t][column c]
    int tid = threadIdx.x;

    if (tid < 32) {
        int m = tid >> 4;       // 0 = q, 1 = k
        int c = tid & 15;       // column = input basis state
        const float* W = m ? Wk : Wq;

        float vr[16], vi[16];
#pragma unroll
        for (int s = 0; s < 16; s++) { vr[s] = (s == c) ? 1.0f : 0.0f; vi[s] = 0.0f; }

#pragma unroll
        for (int layer = 0; layer < 2; layer++) {
#pragma unroll
            for (int w = 0; w < 4; w++) {
                float phi = W[layer * 12 + w * 3 + 0];
                float th  = W[layer * 12 + w * 3 + 1];
                float om  = W[layer * 12 + w * 3 + 2];
                float cth, sth; __sincosf(0.5f * th, &sth, &cth);
                float sA, cA, sB, cB;
                __sincosf(0.5f * (phi + om), &sA, &cA);
                __sincosf(0.5f * (phi - om), &sB, &cB);
                float u00r =  cA * cth, u00i = -sA * cth;
                float u01r = -cB * sth, u01i = -sB * sth;
                float u10r =  cB * sth, u10i = -sB * sth;
                float u11r =  cA * cth, u11i =  sA * cth;
                const int st = 8 >> w;
#pragma unroll
                for (int s = 0; s < 16; s++) {
                    if (!(s & st)) {
                        const int s1 = s | st;
                        float xr = vr[s], xi = vi[s], yr = vr[s1], yi = vi[s1];
                        vr[s]  = u00r * xr - u00i * xi + u01r * yr - u01i * yi;
                        vi[s]  = u00r * xi + u00i * xr + u01r * yi + u01i * yr;
                        vr[s1] = u10r * xr - u10i * xi + u11r * yr - u11i * yi;
                        vi[s1] = u10r * xi + u10i * xr + u11r * yi + u11i * yr;
                    }
                }
            }
#pragma unroll
            for (int w = 0; w < 3; w++) {
                const int cm = 8 >> w, tm = 4 >> w;
#pragma unroll
                for (int s = 0; s < 16; s++) {
                    if ((s & cm) && !(s & tm)) {
                        const int s1 = s | tm;
                        float tr = vr[s], ti = vi[s];
                        vr[s] = vr[s1]; vi[s] = vi[s1];
                        vr[s1] = tr;    vi[s1] = ti;
                    }
                }
            }
        }
#pragma unroll
        for (int t = 0; t < 16; t++) U[m][t][c] = make_float2(vr[t], vi[t]);
    }
    __syncthreads();

    // M[i][j] = sum_t conj(Uq[t][i]) * Uk[t][j]
    int i = tid >> 4, j = tid & 15;
    float mr = 0.0f, mi = 0.0f;
#pragma unroll
    for (int t = 0; t < 16; t++) {
        float2 q = U[0][t][i];
        float2 k = U[1][t][j];
        mr += q.x * k.x + q.y * k.y;
        mi += q.x * k.y - q.y * k.x;
    }
    g_Mr[i * 16 + j] = mr;
    g_Mi[i * 16 + j] = mi;
}

// Build b-side packed pairs and a-side factors for one element.
__device__ __forceinline__ void build_ab(float4 qv, float4 kv,
                                         float* a01, float* a23,
                                         unsigned long long* bp) {
    const float HP = 1.5707963267948966f;  // pi/2
    float cs[4], sn[4];
    __sincosf(fast_tanh(qv.x) * HP, &sn[0], &cs[0]);
    __sincosf(fast_tanh(qv.y) * HP, &sn[1], &cs[1]);
    __sincosf(fast_tanh(qv.z) * HP, &sn[2], &cs[2]);
    __sincosf(fast_tanh(qv.w) * HP, &sn[3], &cs[3]);
    a01[0] = cs[0]*cs[1]; a01[1] = cs[0]*sn[1]; a01[2] = sn[0]*cs[1]; a01[3] = sn[0]*sn[1];
    a23[0] = cs[2]*cs[3]; a23[1] = cs[2]*sn[3]; a23[2] = sn[2]*cs[3]; a23[3] = sn[2]*sn[3];

    __sincosf(fast_tanh(kv.x) * HP, &sn[0], &cs[0]);
    __sincosf(fast_tanh(kv.y) * HP, &sn[1], &cs[1]);
    __sincosf(fast_tanh(kv.z) * HP, &sn[2], &cs[2]);
    __sincosf(fast_tanh(kv.w) * HP, &sn[3], &cs[3]);
    float b01[4] = {cs[0]*cs[1], cs[0]*sn[1], sn[0]*cs[1], sn[0]*sn[1]};
    float b23[4] = {cs[2]*cs[3], cs[2]*sn[3], sn[2]*cs[3], sn[2]*sn[3]};
#pragma unroll
    for (int p = 0; p < 8; p++) {
        int j0 = 2 * p, j1 = 2 * p + 1;
        bp[p] = pk2(b01[j0 >> 2] * b23[j0 & 3], b01[j1 >> 2] * b23[j1 & 3]);
    }
}

// ---------------------------------------------------------------------------
// Main kernel: 2 elements/thread (e, e+128), 128-thr blocks, grid = B/256.
// All 4 input LDGs front-batched; M loop fused across both elements so each
// LDS.128 pair feeds 8 independent fma2 (4 chains). launch_bounds(128,7)
// -> ~6.9 blocks/SM resident = one balanced wave.
// ---------------------------------------------------------------------------
__global__ void __launch_bounds__(128, 7) qdp_main(
        const float4* __restrict__ q4, const float4* __restrict__ k4,
        float* __restrict__ out, int B) {
    // MshR[i*4+c].x = (Mr[i][4c],Mr[i][4c+1]), .y = (Mr[i][4c+2],Mr[i][4c+3])
    __shared__ ulonglong2 MshR[64];
    __shared__ ulonglong2 MshI[64];

    const int tid = threadIdx.x;
    const int base = blockIdx.x * 256;
    const int e0r = base + tid;          // element 0
    const int e1r = base + 128 + tid;    // element 1
    const int e0 = (e0r < B) ? e0r : (B - 1);
    const int e1 = (e1r < B) ? e1r : (B - 1);

    // Front-batched input loads: rows are 64 floats = 16 float4, take #0.
    float4 q0 = __ldcs(&q4[(size_t)e0 * 16]);
    float4 k0 = __ldcs(&k4[(size_t)e0 * 16]);
    float4 q1 = __ldcs(&q4[(size_t)e1 * 16]);
    float4 k1 = __ldcs(&k4[(size_t)e1 * 16]);

    // cooperative M load: 512 floats = 128 x 16B
    {
        const float4* gr = (const float4*)g_Mr;   // 64 float4
        const float4* gi = (const float4*)g_Mi;   // 64 float4
        if (tid < 64) ((float4*)MshR)[tid] = gr[tid];
        else          ((float4*)MshI)[tid - 64] = gi[tid - 64];
    }
    __syncthreads();

    float a01_0[4], a23_0[4], a01_1[4], a23_1[4];
    unsigned long long bp0[8], bp1[8];
    build_ab(q0, k0, a01_0, a23_0, bp0);
    build_ab(q1, k1, a01_1, a23_1, bp1);

    unsigned long long ovr0 = 0ULL, ovi0 = 0ULL, ovr1 = 0ULL, ovi1 = 0ULL;
#pragma unroll
    for (int i = 0; i < 16; i++) {
        unsigned long long tr0 = 0ULL, ti0 = 0ULL, tr1 = 0ULL, ti1 = 0ULL;
#pragma unroll
        for (int c = 0; c < 4; c++) {
            ulonglong2 mr = MshR[i * 4 + c];
            ulonglong2 mi = MshI[i * 4 + c];
            tr0 = fma2(mr.x, bp0[2 * c + 0], tr0);
            tr1 = fma2(mr.x, bp1[2 * c + 0], tr1);
            ti0 = fma2(mi.x, bp0[2 * c + 0], ti0);
            ti1 = fma2(mi.x, bp1[2 * c + 0], ti1);
            tr0 = fma2(mr.y, bp0[2 * c + 1], tr0);
            tr1 = fma2(mr.y, bp1[2 * c + 1], tr1);
            ti0 = fma2(mi.y, bp0[2 * c + 1], ti0);
            ti1 = fma2(mi.y, bp1[2 * c + 1], ti1);
        }
        float av0 = a01_0[i >> 2] * a23_0[i & 3];
        float av1 = a01_1[i >> 2] * a23_1[i & 3];
        unsigned long long av0p = pk2(av0, av0);
        unsigned long long av1p = pk2(av1, av1);
        ovr0 = fma2(av0p, tr0, ovr0);
        ovi0 = fma2(av0p, ti0, ovi0);
        ovr1 = fma2(av1p, tr1, ovr1);
        ovi1 = fma2(av1p, ti1, ovi1);
    }

    {
        float2 r2 = upk2(ovr0), i2 = upk2(ovi0);
        float re = r2.x + r2.y, im = i2.x + i2.y;
        float score = fmaf(re, re, im * im);
        if (e0r < B) out[e0r] = fmaf(0.5f, score, 0.5f);
    }
    {
        float2 r2 = upk2(ovr1), i2 = upk2(ovi1);
        float re = r2.x + r2.y, im = i2.x + i2.y;
        float score = fmaf(re, re, im * im);
        if (e1r < B) out[e1r] = fmaf(0.5f, score, 0.5f);
    }
}

extern "C" void kernel_launch(void* const* d_in, const int* in_sizes, int n_in,
                              void* d_out, int out_size) {
    const float* q  = (const float*)d_in[0];
    const float* k  = (const float*)d_in[1];
    const float* Wq = (const float*)d_in[2];
    const float* Wk = (const float*)d_in[3];
    int B = in_sizes[0] / 64;

    qdp_prep<<<1, 256>>>(Wq, Wk);
    qdp_main<<<(B + 255) / 256, 128>>>((const float4*)q, (const float4*)k,
                                       (float*)d_out, B);
}